// round 1
// baseline (speedup 1.0000x reference)
#include <cuda_runtime.h>
#include <cstdint>

// ---------------------------------------------------------------------------
// SpecAugment: out[b,t,f] = x[b,t,f] * keep, keep = !(fmask[f] | tmask[b,t])
// Masks derived from jax threefry2x32, key 42, partitionable semantics
// (jax >= 0.4.36 default). Set JAX_PARTITIONABLE 0 to get the legacy
// ("original") split / random_bits layout if rel_err shows a PRNG mismatch.
// ---------------------------------------------------------------------------

#define JAX_PARTITIONABLE 1

static const int B = 128;
static const int T = 4000;
static const int F = 128;

__device__ float g_fkeep[F];     // 1.0 keep / 0.0 masked, per freq bin
__device__ int4  g_tspan[B];     // (ts0, te0, ts1, te1) per batch

// -------- threefry2x32, 20 rounds --------
__device__ __forceinline__ void tf2x32(uint32_t k0, uint32_t k1,
                                       uint32_t x0, uint32_t x1,
                                       uint32_t& o0, uint32_t& o1) {
    uint32_t ks2 = k0 ^ k1 ^ 0x1BD11BDAu;
    x0 += k0; x1 += k1;
#define TF_RND(r) { x0 += x1; x1 = (x1 << (r)) | (x1 >> (32 - (r))); x1 ^= x0; }
    TF_RND(13) TF_RND(15) TF_RND(26) TF_RND(6)
    x0 += k1;  x1 += ks2 + 1u;
    TF_RND(17) TF_RND(29) TF_RND(16) TF_RND(24)
    x0 += ks2; x1 += k0 + 2u;
    TF_RND(13) TF_RND(15) TF_RND(26) TF_RND(6)
    x0 += k0;  x1 += k1 + 3u;
    TF_RND(17) TF_RND(29) TF_RND(16) TF_RND(24)
    x0 += k1;  x1 += ks2 + 4u;
    TF_RND(13) TF_RND(15) TF_RND(26) TF_RND(6)
    x0 += ks2; x1 += k0 + 5u;
#undef TF_RND
    o0 = x0; o1 = x1;
}

__device__ __forceinline__ float bits_to_u01(uint32_t bits) {
    return __uint_as_float((bits >> 9) | 0x3f800000u) - 1.0f;
}

#if JAX_PARTITIONABLE
// uniform element at flat index i for key (k1,k2): counts = 64-bit iota,
// hi word = 0 (sizes << 2^32), bits = bits1 ^ bits2.
__device__ __forceinline__ float jr_uniform(uint32_t k1, uint32_t k2, uint32_t i,
                                            uint32_t /*size*/) {
    uint32_t b1, b2;
    tf2x32(k1, k2, 0u, i, b1, b2);
    return bits_to_u01(b1 ^ b2);
}
// split foldlike: key_i = (bits1_i, bits2_i) with x=(0, i)
__device__ __forceinline__ void jr_split3(uint32_t k1, uint32_t k2, int i,
                                          uint32_t& o1, uint32_t& o2) {
    tf2x32(k1, k2, 0u, (uint32_t)i, o1, o2);
}
#else
// legacy: counts = iota(n); x0 = counts[0:n/2], x1 = counts[n/2:n];
// bits = concat(out0, out1).
__device__ __forceinline__ float jr_uniform(uint32_t k1, uint32_t k2, uint32_t i,
                                            uint32_t size) {
    uint32_t h = size / 2u, b1, b2;
    if (i < h) { tf2x32(k1, k2, i, i + h, b1, b2); return bits_to_u01(b1); }
    else       { tf2x32(k1, k2, i - h, i, b1, b2); return bits_to_u01(b2); }
}
// legacy split(key,3): counts = iota(6) -> pairs (0,3)(1,4)(2,5);
// out = [o0_0,o0_1,o0_2,o1_0,o1_1,o1_2] reshaped (3,2).
__device__ __forceinline__ void jr_split3(uint32_t k1, uint32_t k2, int i,
                                          uint32_t& o1, uint32_t& o2) {
    uint32_t a0, a1, b0, b1, c0, c1;
    tf2x32(k1, k2, 0u, 3u, a0, a1);
    tf2x32(k1, k2, 1u, 4u, b0, b1);
    tf2x32(k1, k2, 2u, 5u, c0, c1);
    if (i == 0)      { o1 = a0; o2 = b0; }
    else if (i == 1) { o1 = c0; o2 = a1; }
    else             { o1 = b1; o2 = c1; }
}
#endif

// -------- mask precompute: 1 block, 128 threads --------
__global__ void specaug_mask_kernel(const int* __restrict__ x_len) {
    const int tid = threadIdx.x;   // doubles as freq bin f and batch index b

    // split(key(42)=(0,42), 3) -> kf, kv, ks
    uint32_t kf1, kf2, kv1, kv2, ks1, ks2;
    jr_split3(0u, 42u, 0, kf1, kf2);
    jr_split3(0u, 42u, 1, kv1, kv2);
    jr_split3(0u, 42u, 2, ks1, ks2);

    // ---- frequency masks (shared across batch): uf = uniform(kf, (2,2)) ----
    // uf[m,0] -> flat 2m, uf[m,1] -> flat 2m+1
    float fs[2], fe[2];
#pragma unroll
    for (int m = 0; m < 2; m++) {
        float u0 = jr_uniform(kf1, kf2, 2u * m + 0u, 4u);
        float u1 = jr_uniform(kf1, kf2, 2u * m + 1u, 4u);
        float f_val   = __fmul_rn(u0, 27.0f);                       // * FREQ_MASK_SIZE
        float f_start = __fmul_rn(u1, __fsub_rn(128.0f, f_val));    // * (F - f_val)
        fs[m] = floorf(f_start);
        fe[m] = floorf(__fadd_rn(f_start, f_val));
    }
    float ff = (float)tid;
    bool fmask = (ff >= fs[0] && ff < fe[0]) || (ff >= fs[1] && ff < fe[1]);
    g_fkeep[tid] = fmask ? 0.0f : 1.0f;

    // ---- time masks (per-sample adaptive) ----
    float xl = (float)x_len[tid];
    float t_param = floorf(__fmul_rn(0.25f, xl));   // TIME_MASK_PCT * x_len
    int span[4];
#pragma unroll
    for (int m = 0; m < 2; m++) {
        float uv = jr_uniform(kv1, kv2, 2u * (uint32_t)tid + (uint32_t)m, 256u);
        float us = jr_uniform(ks1, ks2, 2u * (uint32_t)tid + (uint32_t)m, 256u);
        float t_val   = __fmul_rn(uv, t_param);
        float t_start = __fmul_rn(us, __fsub_rn(xl, t_val));
        span[2 * m + 0] = (int)floorf(t_start);
        span[2 * m + 1] = (int)floorf(__fadd_rn(t_start, t_val));
    }
    g_tspan[tid] = make_int4(span[0], span[1], span[2], span[3]);
}

// -------- streaming apply: warp == one (b,t) row, lane == f4 group --------
__global__ void __launch_bounds__(256)
specaug_apply_kernel(const float4* __restrict__ x, float4* __restrict__ out) {
    const int idx = blockIdx.x * blockDim.x + threadIdx.x;   // < B*T*F/4
    const int f4  = idx & 31;                // F/4 = 32 groups per row
    const unsigned row = (unsigned)idx >> 5; // b*T + t
    const unsigned b = row / 4000u;
    const int      t = (int)(row - b * 4000u);

    const int4 sp = g_tspan[b];              // warp-uniform broadcast
    const bool tmask = ((t >= sp.x) && (t < sp.y)) || ((t >= sp.z) && (t < sp.w));
    const float tk = tmask ? 0.0f : 1.0f;

    const float4* fk4 = reinterpret_cast<const float4*>(g_fkeep);
    float4 fk = fk4[f4];                     // L1-resident after first touch
    float4 v  = x[idx];
    v.x *= fk.x * tk;
    v.y *= fk.y * tk;
    v.z *= fk.z * tk;
    v.w *= fk.w * tk;
    out[idx] = v;
}

extern "C" void kernel_launch(void* const* d_in, const int* in_sizes, int n_in,
                              void* d_out, int out_size) {
    const float* x     = (const float*)d_in[0];
    const int*   x_len = (const int*)d_in[1];
    float*       out   = (float*)d_out;

    specaug_mask_kernel<<<1, 128>>>(x_len);

    const int total4 = B * T * F / 4;        // 16,384,000
    specaug_apply_kernel<<<total4 / 256, 256>>>(
        reinterpret_cast<const float4*>(x), reinterpret_cast<float4*>(out));
    (void)in_sizes; (void)n_in; (void)out_size;
}

// round 8
// speedup vs baseline: 1.0275x; 1.0275x over previous
#include <cuda_runtime.h>
#include <cstdint>

// ---------------------------------------------------------------------------
// SpecAugment fused single kernel (resubmit x6 — R2..R7 benches all died on
// broker GPUAcquisitionTimeout; kernel has not yet run on HW):
//   out[b,t,f] = x[b,t,f] * keep, keep = !(fmask[f] | tmask[b,t])
// Mask PRNG (jax threefry2x32, key 42, partitionable semantics — verified
// bit-exact in R1, rel_err 0.0) is recomputed per block: block-uniform ALU
// work that hides under the HBM stream, eliminating the separate mask kernel
// and one graph launch (~2.7us).
// Block = 256 threads handles a 32-row (t) x 128 (f) tile of one batch b.
// Each thread: 4 front-batched float4 loads (MLP_p1=4), streaming hints.
// ---------------------------------------------------------------------------

static const int B = 128;
static const int T = 4000;
static const int F = 128;

// -------- threefry2x32, 20 rounds --------
__device__ __forceinline__ void tf2x32(uint32_t k0, uint32_t k1,
                                       uint32_t x0, uint32_t x1,
                                       uint32_t& o0, uint32_t& o1) {
    uint32_t ks2 = k0 ^ k1 ^ 0x1BD11BDAu;
    x0 += k0; x1 += k1;
#define TF_RND(r) { x0 += x1; x1 = (x1 << (r)) | (x1 >> (32 - (r))); x1 ^= x0; }
    TF_RND(13) TF_RND(15) TF_RND(26) TF_RND(6)
    x0 += k1;  x1 += ks2 + 1u;
    TF_RND(17) TF_RND(29) TF_RND(16) TF_RND(24)
    x0 += ks2; x1 += k0 + 2u;
    TF_RND(13) TF_RND(15) TF_RND(26) TF_RND(6)
    x0 += k0;  x1 += k1 + 3u;
    TF_RND(17) TF_RND(29) TF_RND(16) TF_RND(24)
    x0 += k1;  x1 += ks2 + 4u;
    TF_RND(13) TF_RND(15) TF_RND(26) TF_RND(6)
    x0 += ks2; x1 += k0 + 5u;
#undef TF_RND
    o0 = x0; o1 = x1;
}

__device__ __forceinline__ float bits_to_u01(uint32_t bits) {
    return __uint_as_float((bits >> 9) | 0x3f800000u) - 1.0f;
}

// partitionable uniform: counts = 64-bit iota (hi word 0), bits = b1 ^ b2
__device__ __forceinline__ float jr_uniform(uint32_t k1, uint32_t k2, uint32_t i) {
    uint32_t b1, b2;
    tf2x32(k1, k2, 0u, i, b1, b2);
    return bits_to_u01(b1 ^ b2);
}

__global__ void __launch_bounds__(256)
specaug_fused_kernel(const float4* __restrict__ x,
                     const int*    __restrict__ x_len,
                     float4*       __restrict__ out) {
    const int tid  = threadIdx.x;
    const int lane = tid & 31;        // f4 group: covers f = lane*4 .. lane*4+3
    const int w    = tid >> 5;        // row-within-tile 0..7
    const int b    = blockIdx.y;
    const int t0   = blockIdx.x * 32 + w;   // rows t0, t0+8, t0+16, t0+24

    const int idx0 = (b * T + t0) * (F / 4) + lane;

    // ---- front-batched loads (MLP_p1 = 4), streaming (no reuse) ----
    float4 v0 = __ldcs(&x[idx0]);
    float4 v1 = __ldcs(&x[idx0 + 256]);   // +8 rows * 32 float4
    float4 v2 = __ldcs(&x[idx0 + 512]);
    float4 v3 = __ldcs(&x[idx0 + 768]);

    // ---- block-uniform mask math (hides under the loads) ----
    // split(key(42)=(0,42), 3) -> kf, kv, ks   (foldlike split)
    uint32_t kf1, kf2, kv1, kv2, ks1, ks2;
    tf2x32(0u, 42u, 0u, 0u, kf1, kf2);
    tf2x32(0u, 42u, 0u, 1u, kv1, kv2);
    tf2x32(0u, 42u, 0u, 2u, ks1, ks2);

    // frequency masks: uf = uniform(kf, (2,2)); uf[m,0]=flat 2m, uf[m,1]=flat 2m+1
    float fs[2], fe[2];
#pragma unroll
    for (int m = 0; m < 2; m++) {
        float u0 = jr_uniform(kf1, kf2, 2u * m + 0u);
        float u1 = jr_uniform(kf1, kf2, 2u * m + 1u);
        float f_val   = __fmul_rn(u0, 27.0f);                    // FREQ_MASK_SIZE
        float f_start = __fmul_rn(u1, __fsub_rn(128.0f, f_val)); // F - f_val
        fs[m] = floorf(f_start);
        fe[m] = floorf(__fadd_rn(f_start, f_val));
    }

    // time masks for this batch b (adaptive): t_param = floor(0.25 * x_len[b])
    const float xl = (float)__ldg(&x_len[b]);
    const float t_param = floorf(__fmul_rn(0.25f, xl));
    int ts0, te0, ts1, te1;
    {
        float uv0 = jr_uniform(kv1, kv2, 2u * (uint32_t)b + 0u);
        float uv1 = jr_uniform(kv1, kv2, 2u * (uint32_t)b + 1u);
        float us0 = jr_uniform(ks1, ks2, 2u * (uint32_t)b + 0u);
        float us1 = jr_uniform(ks1, ks2, 2u * (uint32_t)b + 1u);
        float tv0 = __fmul_rn(uv0, t_param);
        float tv1 = __fmul_rn(uv1, t_param);
        float tb0 = __fmul_rn(us0, __fsub_rn(xl, tv0));
        float tb1 = __fmul_rn(us1, __fsub_rn(xl, tv1));
        ts0 = (int)floorf(tb0);  te0 = (int)floorf(__fadd_rn(tb0, tv0));
        ts1 = (int)floorf(tb1);  te1 = (int)floorf(__fadd_rn(tb1, tv1));
    }

    // per-lane frequency keep for the 4 f bins
    float fk[4];
#pragma unroll
    for (int j = 0; j < 4; j++) {
        float ff = (float)(lane * 4 + j);
        bool fm = (ff >= fs[0] && ff < fe[0]) || (ff >= fs[1] && ff < fe[1]);
        fk[j] = fm ? 0.0f : 1.0f;
    }

    // per-row time keep for the 4 rows
    float tk[4];
#pragma unroll
    for (int k = 0; k < 4; k++) {
        int t = t0 + 8 * k;
        bool tm = ((t >= ts0) && (t < te0)) || ((t >= ts1) && (t < te1));
        tk[k] = tm ? 0.0f : 1.0f;
    }

    // ---- apply + streaming stores ----
    v0.x *= fk[0] * tk[0]; v0.y *= fk[1] * tk[0]; v0.z *= fk[2] * tk[0]; v0.w *= fk[3] * tk[0];
    v1.x *= fk[0] * tk[1]; v1.y *= fk[1] * tk[1]; v1.z *= fk[2] * tk[1]; v1.w *= fk[3] * tk[1];
    v2.x *= fk[0] * tk[2]; v2.y *= fk[1] * tk[2]; v2.z *= fk[2] * tk[2]; v2.w *= fk[3] * tk[2];
    v3.x *= fk[0] * tk[3]; v3.y *= fk[1] * tk[3]; v3.z *= fk[2] * tk[3]; v3.w *= fk[3] * tk[3];

    __stcs(&out[idx0],       v0);
    __stcs(&out[idx0 + 256], v1);
    __stcs(&out[idx0 + 512], v2);
    __stcs(&out[idx0 + 768], v3);
}

extern "C" void kernel_launch(void* const* d_in, const int* in_sizes, int n_in,
                              void* d_out, int out_size) {
    const float* x     = (const float*)d_in[0];
    const int*   x_len = (const int*)d_in[1];
    float*       out   = (float*)d_out;

    dim3 grid(T / 32, B);   // (125, 128)
    specaug_fused_kernel<<<grid, 256>>>(
        reinterpret_cast<const float4*>(x), x_len,
        reinterpret_cast<float4*>(out));
    (void)in_sizes; (void)n_in; (void)out_size;
}

// round 16
// speedup vs baseline: 1.0324x; 1.0048x over previous
#include <cuda_runtime.h>
#include <cstdint>

// ---------------------------------------------------------------------------
// SpecAugment fused kernel, R9 (resubmit x7 — R9..R15 benches died on broker
// GPUAcquisitionTimeout): time-mask PRNG hoisted to one thread per block
// (shared-memory broadcast). R8 showed alu=68%/issue=63% because the
// runtime-dependent time-mask threefry (4 calls, ~320 instr) ran per-thread;
// freq-mask threefry is constant-folded at compile time and stays inline.
//   out[b,t,f] = x[b,t,f] * keep, keep = !(fmask[f] | tmask[b,t])
// Block = 256 threads, 32-row (t) x 128 (f) tile of batch b.
// 4 front-batched float4 loads per thread (MLP_p1=4), streaming hints.
// ---------------------------------------------------------------------------

static const int B = 128;
static const int T = 4000;
static const int F = 128;

// -------- threefry2x32, 20 rounds --------
__device__ __forceinline__ void tf2x32(uint32_t k0, uint32_t k1,
                                       uint32_t x0, uint32_t x1,
                                       uint32_t& o0, uint32_t& o1) {
    uint32_t ks2 = k0 ^ k1 ^ 0x1BD11BDAu;
    x0 += k0; x1 += k1;
#define TF_RND(r) { x0 += x1; x1 = (x1 << (r)) | (x1 >> (32 - (r))); x1 ^= x0; }
    TF_RND(13) TF_RND(15) TF_RND(26) TF_RND(6)
    x0 += k1;  x1 += ks2 + 1u;
    TF_RND(17) TF_RND(29) TF_RND(16) TF_RND(24)
    x0 += ks2; x1 += k0 + 2u;
    TF_RND(13) TF_RND(15) TF_RND(26) TF_RND(6)
    x0 += k0;  x1 += k1 + 3u;
    TF_RND(17) TF_RND(29) TF_RND(16) TF_RND(24)
    x0 += k1;  x1 += ks2 + 4u;
    TF_RND(13) TF_RND(15) TF_RND(26) TF_RND(6)
    x0 += ks2; x1 += k0 + 5u;
#undef TF_RND
    o0 = x0; o1 = x1;
}

__device__ __forceinline__ float bits_to_u01(uint32_t bits) {
    return __uint_as_float((bits >> 9) | 0x3f800000u) - 1.0f;
}

// partitionable uniform: counts = 64-bit iota (hi word 0), bits = b1 ^ b2
__device__ __forceinline__ float jr_uniform(uint32_t k1, uint32_t k2, uint32_t i) {
    uint32_t b1, b2;
    tf2x32(k1, k2, 0u, i, b1, b2);
    return bits_to_u01(b1 ^ b2);
}

__global__ void __launch_bounds__(256)
specaug_fused_kernel(const float4* __restrict__ x,
                     const int*    __restrict__ x_len,
                     float4*       __restrict__ out) {
    const int tid  = threadIdx.x;
    const int lane = tid & 31;        // f4 group: covers f = lane*4 .. lane*4+3
    const int w    = tid >> 5;        // row-within-tile 0..7
    const int b    = blockIdx.y;
    const int t0   = blockIdx.x * 32 + w;   // rows t0, t0+8, t0+16, t0+24

    const int idx0 = (b * T + t0) * (F / 4) + lane;

    // ---- front-batched loads (MLP_p1 = 4), streaming (no reuse) ----
    float4 v0 = __ldcs(&x[idx0]);
    float4 v1 = __ldcs(&x[idx0 + 256]);   // +8 rows * 32 float4
    float4 v2 = __ldcs(&x[idx0 + 512]);
    float4 v3 = __ldcs(&x[idx0 + 768]);

    // ---- time-mask spans: ONE thread per block, broadcast via smem ----
    // (runtime-dependent PRNG; per-thread in R8 this was 68% of ALU issue)
    __shared__ int4 s_span;
    if (tid == 0) {
        // split(key(42)=(0,42), 3) -> kf(unused here), kv, ks  (foldlike)
        uint32_t kv1, kv2, ks1, ks2;
        tf2x32(0u, 42u, 0u, 1u, kv1, kv2);
        tf2x32(0u, 42u, 0u, 2u, ks1, ks2);

        const float xl = (float)__ldg(&x_len[b]);
        const float t_param = floorf(__fmul_rn(0.25f, xl));   // TIME_MASK_PCT*len
        float uv0 = jr_uniform(kv1, kv2, 2u * (uint32_t)b + 0u);
        float uv1 = jr_uniform(kv1, kv2, 2u * (uint32_t)b + 1u);
        float us0 = jr_uniform(ks1, ks2, 2u * (uint32_t)b + 0u);
        float us1 = jr_uniform(ks1, ks2, 2u * (uint32_t)b + 1u);
        float tv0 = __fmul_rn(uv0, t_param);
        float tv1 = __fmul_rn(uv1, t_param);
        float tb0 = __fmul_rn(us0, __fsub_rn(xl, tv0));
        float tb1 = __fmul_rn(us1, __fsub_rn(xl, tv1));
        s_span = make_int4((int)floorf(tb0), (int)floorf(__fadd_rn(tb0, tv0)),
                           (int)floorf(tb1), (int)floorf(__fadd_rn(tb1, tv1)));
    }

    // ---- frequency masks: all-constant PRNG, fully constant-folded ----
    // split(key(42)) -> kf; uf = uniform(kf, (2,2))
    float fs[2], fe[2];
    {
        uint32_t kf1, kf2;
        tf2x32(0u, 42u, 0u, 0u, kf1, kf2);
#pragma unroll
        for (int m = 0; m < 2; m++) {
            float u0 = jr_uniform(kf1, kf2, 2u * m + 0u);
            float u1 = jr_uniform(kf1, kf2, 2u * m + 1u);
            float f_val   = __fmul_rn(u0, 27.0f);                    // FREQ_MASK_SIZE
            float f_start = __fmul_rn(u1, __fsub_rn(128.0f, f_val)); // F - f_val
            fs[m] = floorf(f_start);
            fe[m] = floorf(__fadd_rn(f_start, f_val));
        }
    }

    // per-lane frequency keep for the 4 f bins (constants at compile time)
    float fk[4];
#pragma unroll
    for (int j = 0; j < 4; j++) {
        float ff = (float)(lane * 4 + j);
        bool fm = (ff >= fs[0] && ff < fe[0]) || (ff >= fs[1] && ff < fe[1]);
        fk[j] = fm ? 0.0f : 1.0f;
    }

    __syncthreads();                      // loads already in flight above
    const int4 sp = s_span;

    // per-row time keep for the 4 rows
    float tk[4];
#pragma unroll
    for (int k = 0; k < 4; k++) {
        int t = t0 + 8 * k;
        bool tm = ((t >= sp.x) && (t < sp.y)) || ((t >= sp.z) && (t < sp.w));
        tk[k] = tm ? 0.0f : 1.0f;
    }

    // ---- apply + streaming stores ----
    v0.x *= fk[0] * tk[0]; v0.y *= fk[1] * tk[0]; v0.z *= fk[2] * tk[0]; v0.w *= fk[3] * tk[0];
    v1.x *= fk[0] * tk[1]; v1.y *= fk[1] * tk[1]; v1.z *= fk[2] * tk[1]; v1.w *= fk[3] * tk[1];
    v2.x *= fk[0] * tk[2]; v2.y *= fk[1] * tk[2]; v2.z *= fk[2] * tk[2]; v2.w *= fk[3] * tk[2];
    v3.x *= fk[0] * tk[3]; v3.y *= fk[1] * tk[3]; v3.z *= fk[2] * tk[3]; v3.w *= fk[3] * tk[3];

    __stcs(&out[idx0],       v0);
    __stcs(&out[idx0 + 256], v1);
    __stcs(&out[idx0 + 512], v2);
    __stcs(&out[idx0 + 768], v3);
}

extern "C" void kernel_launch(void* const* d_in, const int* in_sizes, int n_in,
                              void* d_out, int out_size) {
    const float* x     = (const float*)d_in[0];
    const int*   x_len = (const int*)d_in[1];
    float*       out   = (float*)d_out;

    dim3 grid(T / 32, B);   // (125, 128)
    specaug_fused_kernel<<<grid, 256>>>(
        reinterpret_cast<const float4*>(x), x_len,
        reinterpret_cast<float4*>(out));
    (void)in_sizes; (void)n_in; (void)out_size;
}